// round 6
// baseline (speedup 1.0000x reference)
#include <cuda_runtime.h>

#define BATCH 32
#define KC 16
#define TIMESTEPS 8

// Membrane arena + activation ping-pong + split-K scratch + transposed weights.
__device__ float g_mem[8257536];
__device__ float g_bufA[2097152];
__device__ float g_bufB[2097152];
__device__ float g_bufC[2097152];
__device__ float g_scratch[2097152];
__device__ float g_wT[4966080];

struct ConvP {
    const float* __restrict__ in;
    const float* __restrict__ wT;     // [k][Cout], k = r*Cin + ci
    float*       out;
    float*       mem;
    const float* __restrict__ res;
    const float* __restrict__ mask;
    const float* __restrict__ thr;
    const float* __restrict__ leak;
    float*       scratch;
    int li;
    int Hin, Win;
    int Cout, Hout, Wout;
    int mode;        // 0 raw, 1 fused LIF, 2 split-K partial
    int cPerZ;       // chunks per z-split
    int N;           // BATCH*Hout*Wout
};

// ============================================================================
// convT: 64co x 128pos tile, 256 threads, 4x8 per-thread block.
// k = r*CIN + ci linearization; CIN templated -> all decode compile-time.
// Double-buffered smem, one sync per chunk. Split-K over blockIdx.z.
// ============================================================================
template<int KH, int STRIDE, int PAD, int CIN>
__global__ __launch_bounds__(256) void convT(ConvP p) {
    constexpr int KK = KH * KH;
    constexpr int K  = KK * CIN;
    constexpr int CTOT = (K + KC - 1) / KC;

    __shared__ __align__(16) float As[2][KC][64];
    __shared__ __align__(16) float Bs[2][KC][128];

    const int tid = threadIdx.x;
    const int tx = tid & 15;
    const int ty = tid >> 4;
    const int pos0 = blockIdx.x * 128;
    const int co0  = blockIdx.y * 64;
    const int HW   = p.Hout * p.Wout;
    const int HWin = p.Hin * p.Win;

    // A loader: one float4 per thread. k row = tid>>4, co = (tid&15)*4.
    const int kA  = tid >> 4;
    const int coA = (tid & 15) * 4;

    // B loader: lp = tid&127 (pos), kq = (tid>>7)*8 (8 k's).
    const int lp = tid & 127;
    const int kq = (tid >> 7) * 8;
    const int pp  = pos0 + lp;
    const int pb  = pp / HW;
    const int phw = pp - pb * HW;
    const int py  = phw / p.Wout;
    const int px  = phw - py * p.Wout;
    const int iy0 = py * STRIDE - PAD;
    const int ix0 = px * STRIDE - PAD;
    const float* __restrict__ inb = p.in + (size_t)pb * CIN * HWin;

    const int c0 = blockIdx.z * p.cPerZ;
    int c1 = c0 + p.cPerZ; if (c1 > CTOT) c1 = CTOT;

    float4 ra;
    float rb[8];

    auto prefetch = [&](int c) {
        const int k0 = c * KC;
        // A: wT offset is simply k*Cout (k = r*CIN+ci linear order)
        if (CIN >= 16 || k0 + kA < K)
            ra = *(const float4*)(p.wT + (size_t)(k0 + kA) * p.Cout + co0 + coA);
        else
            ra = make_float4(0.f, 0.f, 0.f, 0.f);
        if (CIN >= 16) {
            // whole chunk shares one r (CIN multiple of 16, chunks aligned)
            const int r   = k0 / CIN;             // compile-time shift
            const int ci0 = k0 % CIN;             // compile-time mask
            const int ky  = r / KH;
            const int kx  = r - ky * KH;
            const int iy = iy0 + ky, ix = ix0 + kx;
            const bool ok = (iy >= 0 && iy < p.Hin && ix >= 0 && ix < p.Win);
            const float* src = inb + (size_t)(ci0 + kq) * HWin + iy * p.Win + ix;
#pragma unroll
            for (int i = 0; i < 8; i++)
                rb[i] = ok ? __ldg(src + (size_t)i * HWin) : 0.f;
        } else {
            // small-Cin path (pre0): per-k decode, all divides by constants
#pragma unroll
            for (int i = 0; i < 8; i++) {
                const int k = k0 + kq + i;
                float v = 0.f;
                if (k < K) {
                    const int r  = k / CIN;
                    const int ci = k - r * CIN;
                    const int ky = r / KH;
                    const int kx = r - ky * KH;
                    const int iy = iy0 + ky, ix = ix0 + kx;
                    if (iy >= 0 && iy < p.Hin && ix >= 0 && ix < p.Win)
                        v = __ldg(inb + (size_t)ci * HWin + iy * p.Win + ix);
                }
                rb[i] = v;
            }
        }
    };

    float acc[4][8];
#pragma unroll
    for (int i = 0; i < 4; i++)
#pragma unroll
        for (int j = 0; j < 8; j++) acc[i][j] = 0.f;

    prefetch(c0);
    *(float4*)&As[0][kA][coA] = ra;
#pragma unroll
    for (int i = 0; i < 8; i++) Bs[0][kq + i][lp] = rb[i];

    int s = 0;
    for (int c = c0; c < c1; c++) {
        __syncthreads();
        const bool more = (c + 1 < c1);
        if (more) prefetch(c + 1);
#pragma unroll
        for (int k = 0; k < KC; k++) {
            const float4 a  = *(const float4*)&As[s][k][ty * 4];
            const float4 b0 = *(const float4*)&Bs[s][k][tx * 4];
            const float4 b1 = *(const float4*)&Bs[s][k][64 + tx * 4];
            const float av[4] = {a.x, a.y, a.z, a.w};
            const float bv[8] = {b0.x, b0.y, b0.z, b0.w, b1.x, b1.y, b1.z, b1.w};
#pragma unroll
            for (int i = 0; i < 4; i++)
#pragma unroll
                for (int j = 0; j < 8; j++)
                    acc[i][j] = fmaf(av[i], bv[j], acc[i][j]);
        }
        if (more) {
            *(float4*)&As[s ^ 1][kA][coA] = ra;
#pragma unroll
            for (int i = 0; i < 8; i++) Bs[s ^ 1][kq + i][lp] = rb[i];
        }
        s ^= 1;
    }

    // ---- epilogue ----
    if (p.mode == 2) {
#pragma unroll
        for (int h = 0; h < 2; h++) {
            int posb = pos0 + h * 64 + tx * 4;
            size_t base = ((size_t)blockIdx.z * p.Cout + co0 + ty * 4) * p.N + posb;
#pragma unroll
            for (int i = 0; i < 4; i++)
#pragma unroll
                for (int j = 0; j < 4; j++)
                    p.scratch[base + (size_t)i * p.N + j] = acc[i][h * 4 + j];
        }
        return;
    }

    float th = 1.f, lkf = 1.f;
    if (p.mode == 1) { th = p.thr[p.li]; lkf = p.leak[p.li]; }

#pragma unroll
    for (int h = 0; h < 2; h++) {
        int posb = pos0 + h * 64 + tx * 4;
        int b  = posb / HW;
        int hw = posb - b * HW;
#pragma unroll
        for (int i = 0; i < 4; i++) {
            size_t g = ((size_t)b * p.Cout + co0 + ty * 4 + i) * HW + hw;
#pragma unroll
            for (int j = 0; j < 4; j++) {
                float d = acc[i][h * 4 + j];
                size_t gi = g + j;
                if (p.mode == 0) {
                    p.out[gi] = d;
                } else {
                    if (p.res) d += p.res[gi];
                    float m  = lkf * p.mem[gi] + d;
                    float mt = m / th - 1.f;
                    float sp = (mt > 0.f) ? 1.f : 0.f;
                    p.mem[gi] = m - th * sp;
                    float o = sp;
                    if (p.mask) o *= p.mask[gi];
                    p.out[gi] = o;
                }
            }
        }
    }
}

// ---- fused weight transpose: all 14 weights in one launch ----
struct WTArgs { const float* src[14]; float* dst; };

__global__ void wt_all(WTArgs a) {
    const int off[15] = {0, 1728, 38592, 75456, 112320, 149184, 222912,
                         370368, 378560, 673472, 1263296, 1296064, 2475712,
                         4835008, 4966080};
    const int coutT[14] = {64,64,64,64,64,128,128,128,256,256,256,512,512,512};
    const int cinT[14]  = {3,64,64,64,64,64,128,64,128,256,128,256,512,256};
    const int kkT[14]   = {9,9,9,9,9,9,9,1,9,9,1,9,9,1};
    int idx = blockIdx.x * blockDim.x + threadIdx.x;
    if (idx >= 4966080) return;
    int s = 0;
    while (idx >= off[s + 1]) s++;
    int local = idx - off[s];
    int CK  = cinT[s] * kkT[s];
    int co  = local / CK;
    int rem = local - co * CK;
    int ci  = rem / kkT[s];
    int r   = rem - ci * kkT[s];
    a.dst[off[s] + ((size_t)r * cinT[s] + ci) * coutT[s] + co] = a.src[s][local];
}

// Combine split-K partials (+ optional residual/mask) + LIF.
__global__ void combine_lif(const float* __restrict__ scratch, int S, int Cout,
                            int N, int HW,
                            const float* __restrict__ res,
                            const float* __restrict__ mask,
                            float* mem, float* out,
                            const float* __restrict__ thr,
                            const float* __restrict__ leak, int li) {
    int idx = blockIdx.x * blockDim.x + threadIdx.x;
    int total = Cout * N;
    if (idx >= total) return;
    int co  = idx / N;
    int pos = idx - co * N;
    float d = 0.f;
    for (int s = 0; s < S; s++)
        d += scratch[((size_t)s * Cout + co) * N + pos];
    int b = pos / HW, hw = pos - b * HW;
    size_t g = ((size_t)b * Cout + co) * HW + hw;
    if (res) d += res[g];
    float th = thr[li], lkf = leak[li];
    float m  = lkf * mem[g] + d;
    float mt = m / th - 1.f;
    float s_ = (mt > 0.f) ? 1.f : 0.f;
    mem[g] = m - th * s_;
    float o = s_;
    if (mask) o *= mask[g];
    out[g] = o;
}

__global__ void zero_mem_kernel(float* mem, int n) {
    int i = blockIdx.x * blockDim.x + threadIdx.x;
    if (i < n) mem[i] = 0.f;
}
__global__ void zero_out_kernel(float* out, int n) {
    int i = blockIdx.x * blockDim.x + threadIdx.x;
    if (i < n) out[i] = 0.f;
}

__global__ void avgpool2_kernel(const float* __restrict__ in, float* out,
                                int C, int H, int W) {
    int Ho = H >> 1, Wo = W >> 1;
    int total = BATCH * C * Ho * Wo;
    int idx = blockIdx.x * blockDim.x + threadIdx.x;
    if (idx >= total) return;
    int x = idx % Wo; int t = idx / Wo;
    int y = t % Ho;   t /= Ho;
    int c = t % C;    int b = t / C;
    const float* pp = in + (((size_t)b * C + c) * H + y * 2) * W + x * 2;
    out[idx] = 0.25f * (pp[0] + pp[1] + pp[W] + pp[W + 1]);
}

__global__ void fc_acc_kernel(const float* __restrict__ o,
                              const float* __restrict__ wfc, float* out) {
    int bk = blockIdx.x;
    int b = bk / 10, k = bk % 10;
    const float* op = o + (size_t)b * 2048;
    const float* wp = wfc + (size_t)k * 2048;
    float s = 0.f;
    for (int j = threadIdx.x; j < 2048; j += 128) s += op[j] * wp[j];
    __shared__ float red[128];
    red[threadIdx.x] = s;
    __syncthreads();
    for (int st = 64; st > 0; st >>= 1) {
        if (threadIdx.x < st) red[threadIdx.x] += red[threadIdx.x + st];
        __syncthreads();
    }
    if (threadIdx.x == 0) out[b * 10 + k] += red[0];
}

// ============================================================================
// Host side
// ============================================================================

static ConvP mkp(const float* in, const float* wT, float* out, float* mem,
                 const float* res, const float* mask,
                 const float* thr, const float* leak, float* scratch, int li,
                 int Hin, int Win, int Cout, int Hout, int Wout,
                 int mode, int cPerZ) {
    ConvP p;
    p.in = in; p.wT = wT; p.out = out; p.mem = mem; p.res = res; p.mask = mask;
    p.thr = thr; p.leak = leak; p.scratch = scratch; p.li = li;
    p.Hin = Hin; p.Win = Win;
    p.Cout = Cout; p.Hout = Hout; p.Wout = Wout;
    p.mode = mode; p.cPerZ = cPerZ;
    p.N = BATCH * Hout * Wout;
    return p;
}

extern "C" void kernel_launch(void* const* d_in, const int* in_sizes, int n_in,
                              void* d_out, int out_size) {
    const float* x      = (const float*)d_in[0];
    const float* w_fc   = (const float*)d_in[15];
    const float* thr    = (const float*)d_in[16];
    const float* leak   = (const float*)d_in[17];
    const float* mask2  = (const float*)d_in[18];
    const float* mask5  = (const float*)d_in[19];
    const float* mask9  = (const float*)d_in[20];
    const float* mask11 = (const float*)d_in[21];
    const float* mask13 = (const float*)d_in[22];
    const float* mask15 = (const float*)d_in[23];

    float *memBase, *bufA, *bufB, *bufC, *scr, *wT;
    cudaGetSymbolAddress((void**)&memBase, g_mem);
    cudaGetSymbolAddress((void**)&bufA, g_bufA);
    cudaGetSymbolAddress((void**)&bufB, g_bufB);
    cudaGetSymbolAddress((void**)&bufC, g_bufC);
    cudaGetSymbolAddress((void**)&scr, g_scratch);
    cudaGetSymbolAddress((void**)&wT, g_wT);
    float* out = (float*)d_out;

    // Launch order: 2 zero kernels, then wt_all, then pre0..pre2 so that
    // ncu's -s 5 -c 1 capture (6th launch) lands on pre2 = hot convT.
    zero_mem_kernel<<<(8257536 + 255) / 256, 256>>>(memBase, 8257536);
    zero_out_kernel<<<2, 256>>>(out, 320);

    WTArgs wa;
    // order: pre0,pre1,pre2,w1a,w1b,w2a,w2b,w2i,w3a,w3b,w3i,w4a,w4b,w4i
    for (int i = 0; i < 14; i++) wa.src[i] = (const float*)d_in[1 + i];
    wa.dst = wT;
    wt_all<<<(4966080 + 255) / 256, 256>>>(wa);

    const float* tpre0 = wT + 0;
    const float* tpre1 = wT + 1728;
    const float* tpre2 = wT + 38592;
    const float* t1a   = wT + 75456;
    const float* t1b   = wT + 112320;
    const float* t2a   = wT + 149184;
    const float* t2b   = wT + 222912;
    const float* t2i   = wT + 370368;
    const float* t3a   = wT + 378560;
    const float* t3b   = wT + 673472;
    const float* t3i   = wT + 1263296;
    const float* t4a   = wT + 1296064;
    const float* t4b   = wT + 2475712;
    const float* t4i   = wT + 4835008;

    float* m0  = memBase + 0;
    float* m1  = memBase + 2097152;
    float* m2  = memBase + 4194304;
    float* m3  = memBase + 6291456;
    float* m4  = memBase + 6815744;
    float* m5  = memBase + 7340032;
    float* m6  = memBase + 7602176;
    float* m7  = memBase + 7864320;
    float* m8  = memBase + 7995392;
    float* m9  = memBase + 8126464;
    float* m10 = memBase + 8192000;

    for (int t = 0; t < TIMESTEPS; t++) {
        ConvP p;
        // ---- pre_process: 3x3 convs @32x32, Cout=64, N=32768 ----
        p = mkp(x, tpre0, bufA, m0, nullptr, mask2, thr, leak, scr, 0,
                32, 32, 64, 32, 32, 1, 2);                       // K=27, 2 chunks
        convT<3,1,1,3><<<dim3(256, 1, 1), 256>>>(p);
        p = mkp(bufA, tpre1, bufB, m1, nullptr, mask5, thr, leak, scr, 1,
                32, 32, 64, 32, 32, 1, 36);
        convT<3,1,1,64><<<dim3(256, 1, 1), 256>>>(p);
        p = mkp(bufB, tpre2, bufA, m2, nullptr, nullptr, thr, leak, scr, 2,
                32, 32, 64, 32, 32, 1, 36);
        convT<3,1,1,64><<<dim3(256, 1, 1), 256>>>(p);
        avgpool2_kernel<<<(BATCH*64*16*16 + 255)/256, 256>>>(bufA, bufB, 64, 32, 32);

        // ---- layer1 (identity shortcut), inp = bufB, 16x16, Cout=64, N=8192 ----
        p = mkp(bufB, t1a, nullptr, nullptr, nullptr, nullptr, thr, leak, scr, 0,
                16, 16, 64, 16, 16, 2, 18);                      // 36 chunks, S=2
        convT<3,1,1,64><<<dim3(64, 1, 2), 256>>>(p);
        combine_lif<<<(64*8192 + 255)/256, 256>>>(scr, 2, 64, 8192, 256,
                nullptr, mask9, m3, bufA, thr, leak, 3);
        p = mkp(bufA, t1b, nullptr, nullptr, nullptr, nullptr, thr, leak, scr, 0,
                16, 16, 64, 16, 16, 2, 18);
        convT<3,1,1,64><<<dim3(64, 1, 2), 256>>>(p);
        combine_lif<<<(64*8192 + 255)/256, 256>>>(scr, 2, 64, 8192, 256,
                bufB, nullptr, m4, bufC, thr, leak, 4);

        // ---- layer2, inp = bufC, out 8x8, Cout=128, N=2048 ----
        p = mkp(bufC, t2i, nullptr, nullptr, nullptr, nullptr, thr, leak,
                scr + (size_t)4*128*2048, 0,
                16, 16, 128, 8, 8, 2, 2);                        // 4 chunks, S=2
        convT<1,2,0,64><<<dim3(16, 2, 2), 256>>>(p);
        p = mkp(bufC, t2a, nullptr, nullptr, nullptr, nullptr, thr, leak, scr, 0,
                16, 16, 128, 8, 8, 2, 9);                        // 36 chunks, S=4
        convT<3,2,1,64><<<dim3(16, 2, 4), 256>>>(p);
        combine_lif<<<(128*2048 + 255)/256, 256>>>(scr, 4, 128, 2048, 64,
                nullptr, mask11, m5, bufA, thr, leak, 5);
        p = mkp(bufA, t2b, nullptr, nullptr, nullptr, nullptr, thr, leak, scr, 0,
                8, 8, 128, 8, 8, 2, 18);                         // 72 chunks, S=4
        convT<3,1,1,128><<<dim3(16, 2, 4), 256>>>(p);
        combine_lif<<<(128*2048 + 255)/256, 256>>>(scr, 6, 128, 2048, 64,
                nullptr, nullptr, m6, bufC, thr, leak, 6);

        // ---- layer3, inp = bufC, out 4x4, Cout=256, N=512 ----
        p = mkp(bufC, t3i, nullptr, nullptr, nullptr, nullptr, thr, leak,
                scr + (size_t)8*256*512, 0,
                8, 8, 256, 4, 4, 2, 2);                          // 8 chunks, S=4
        convT<1,2,0,128><<<dim3(4, 4, 4), 256>>>(p);
        p = mkp(bufC, t3a, nullptr, nullptr, nullptr, nullptr, thr, leak, scr, 0,
                8, 8, 256, 4, 4, 2, 9);                          // 72 chunks, S=8
        convT<3,2,1,128><<<dim3(4, 4, 8), 256>>>(p);
        combine_lif<<<(256*512 + 255)/256, 256>>>(scr, 8, 256, 512, 16,
                nullptr, mask13, m7, bufA, thr, leak, 7);
        p = mkp(bufA, t3b, nullptr, nullptr, nullptr, nullptr, thr, leak, scr, 0,
                4, 4, 256, 4, 4, 2, 18);                         // 144 chunks, S=8
        convT<3,1,1,256><<<dim3(4, 4, 8), 256>>>(p);
        combine_lif<<<(256*512 + 255)/256, 256>>>(scr, 12, 256, 512, 16,
                nullptr, nullptr, m8, bufC, thr, leak, 8);

        // ---- layer4, inp = bufC, out 2x2, Cout=512, N=128 ----
        p = mkp(bufC, t4i, nullptr, nullptr, nullptr, nullptr, thr, leak,
                scr + (size_t)16*512*128, 0,
                4, 4, 512, 2, 2, 2, 2);                          // 16 chunks, S=8
        convT<1,2,0,256><<<dim3(1, 8, 8), 256>>>(p);
        p = mkp(bufC, t4a, nullptr, nullptr, nullptr, nullptr, thr, leak, scr, 0,
                4, 4, 512, 2, 2, 2, 9);                          // 144 chunks, S=16
        convT<3,2,1,256><<<dim3(1, 8, 16), 256>>>(p);
        combine_lif<<<(512*128 + 255)/256, 256>>>(scr, 16, 512, 128, 4,
                nullptr, mask15, m9, bufA, thr, leak, 9);
        p = mkp(bufA, t4b, nullptr, nullptr, nullptr, nullptr, thr, leak, scr, 0,
                2, 2, 512, 2, 2, 2, 18);                         // 288 chunks, S=16
        convT<3,1,1,512><<<dim3(1, 8, 16), 256>>>(p);
        combine_lif<<<(512*128 + 255)/256, 256>>>(scr, 24, 512, 128, 4,
                nullptr, nullptr, m10, bufC, thr, leak, 10);

        // ---- output accumulator ----
        fc_acc_kernel<<<320, 128>>>(bufC, w_fc, out);
    }
}